// round 7
// baseline (speedup 1.0000x reference)
#include <cstdint>
#include <cuda_runtime.h>
#include <cuda_bf16.h>
#include <mma.h>
#include <math.h>

using namespace nvcuda;

// Shapes (fixed): B=16, T=128, L=64, D=768
#define BB 16
#define TT 128
#define LL 64
#define DD 768
#define TG 4

#define NKV (BB * LL * DD)   // 786432
#define NW  (DD * DD)        // 589824

__device__ float g_kfull[NKV];
__device__ float g_ktil [NKV];
__device__ float g_vfull[NKV];
__device__ float g_c    [BB * LL];

// split-bf16 operand storage
__device__ __nv_bfloat16 g_keyh[NKV], g_keyl[NKV];
__device__ __nv_bfloat16 g_valh[NKV], g_vall[NKV];
__device__ __nv_bfloat16 g_wkh [NW],  g_wkl [NW];
__device__ __nv_bfloat16 g_wvh [NW],  g_wvl [NW];
__device__ __nv_bfloat16 g_wqh [NW],  g_wql [NW];
__device__ __nv_bfloat16 g_kfh [NKV], g_kfl [NKV];

// ---------------------------------------------------------------------------
// Split conversion: hi = bf16(x), lo = bf16(x - hi)
// ---------------------------------------------------------------------------
__device__ __forceinline__ void split8(const float* src,
                                       __nv_bfloat16* hi, __nv_bfloat16* lo)
{
    float4 a = *(const float4*)(src);
    float4 b = *(const float4*)(src + 4);
    float v[8] = {a.x, a.y, a.z, a.w, b.x, b.y, b.z, b.w};
    __nv_bfloat16 h[8], l[8];
    #pragma unroll
    for (int i = 0; i < 8; i++) {
        h[i] = __float2bfloat16(v[i]);
        l[i] = __float2bfloat16(v[i] - __bfloat162float(h[i]));
    }
    *(uint4*)hi = *(uint4*)h;
    *(uint4*)lo = *(uint4*)l;
}

__global__ void __launch_bounds__(256) convert_inputs(
    const float* __restrict__ key, const float* __restrict__ value,
    const float* __restrict__ Wk, const float* __restrict__ Wv,
    const float* __restrict__ Wq)
{
    const float* src; __nv_bfloat16 *hi, *lo; int n;
    switch (blockIdx.y) {
        case 0:  src = key;   hi = g_keyh; lo = g_keyl; n = NKV; break;
        case 1:  src = value; hi = g_valh; lo = g_vall; n = NKV; break;
        case 2:  src = Wk;    hi = g_wkh;  lo = g_wkl;  n = NW;  break;
        case 3:  src = Wv;    hi = g_wvh;  lo = g_wvl;  n = NW;  break;
        default: src = Wq;    hi = g_wqh;  lo = g_wql;  n = NW;  break;
    }
    int idx = (blockIdx.x * 256 + threadIdx.x) * 8;
    if (idx >= n) return;
    split8(src + idx, hi + idx, lo + idx);
}

__global__ void __launch_bounds__(256) convert_kf()
{
    int idx = (blockIdx.x * 256 + threadIdx.x) * 8;
    split8(g_kfull + idx, g_kfh + idx, g_kfl + idx);
}

// ---------------------------------------------------------------------------
// Tensor-core NT GEMM on pre-split bf16: C = A @ W^T + bias
// BM=BN=64, BK=32, 128 threads (4 warps, each 32x32).
// c += ah*bh + ah*bl + al*bh.  grid (12, 16, 2).
// ---------------------------------------------------------------------------
__global__ void __launch_bounds__(128) proj_tc_nt(
    const float* __restrict__ b0, const float* __restrict__ b1)
{
    const __nv_bfloat16 *Ah, *Al, *Bh, *Bl; const float* bias; float* C;
    if (blockIdx.z) { Ah = g_valh; Al = g_vall; Bh = g_wvh; Bl = g_wvl; bias = b1; C = g_vfull; }
    else           { Ah = g_keyh; Al = g_keyl; Bh = g_wkh; Bl = g_wkl; bias = b0; C = g_kfull; }

    __shared__ __align__(16) __nv_bfloat16 sAh[64][32], sAl[64][32];
    __shared__ __align__(16) __nv_bfloat16 sBh[64][32], sBl[64][32];
    __shared__ float biasTile[16][64];

    const int tid  = threadIdx.x;
    const int warp = tid >> 5;
    const int wr   = (warp >> 1) * 32;
    const int wc   = (warp & 1) * 32;
    const int row0 = blockIdx.y * 64;
    const int col0 = blockIdx.x * 64;

    {
        int r = tid >> 3, cb = (tid & 7) * 8;
        #pragma unroll
        for (int i = 0; i < 8; i++) biasTile[r][cb + i] = bias[col0 + cb + i];
    }
    __syncthreads();

    wmma::fragment<wmma::accumulator, 16, 16, 16, float> c[2][2];
    #pragma unroll
    for (int i = 0; i < 2; i++)
        #pragma unroll
        for (int j = 0; j < 2; j++)
            wmma::load_matrix_sync(c[i][j], &biasTile[0][wc + 16 * j], 64,
                                   wmma::mem_row_major);

    // loaders: row = tid>>1 (0..63), seg = (tid&1)*16
    const int lr = tid >> 1;
    const int ls = (tid & 1) * 16;
    const __nv_bfloat16* pAh = Ah + (size_t)(row0 + lr) * DD + ls;
    const __nv_bfloat16* pAl = Al + (size_t)(row0 + lr) * DD + ls;
    const __nv_bfloat16* pBh = Bh + (size_t)(col0 + lr) * DD + ls;
    const __nv_bfloat16* pBl = Bl + (size_t)(col0 + lr) * DD + ls;

    uint4 rah0, rah1, ral0, ral1, rbh0, rbh1, rbl0, rbl1;
    #define LOAD8(k0)                                            \
        rah0 = *(const uint4*)(pAh + (k0));                      \
        rah1 = *(const uint4*)(pAh + (k0) + 8);                  \
        ral0 = *(const uint4*)(pAl + (k0));                      \
        ral1 = *(const uint4*)(pAl + (k0) + 8);                  \
        rbh0 = *(const uint4*)(pBh + (k0));                      \
        rbh1 = *(const uint4*)(pBh + (k0) + 8);                  \
        rbl0 = *(const uint4*)(pBl + (k0));                      \
        rbl1 = *(const uint4*)(pBl + (k0) + 8);

    LOAD8(0)

    for (int k0 = 0; k0 < DD; k0 += 32) {
        __syncthreads();
        *(uint4*)&sAh[lr][ls]     = rah0;  *(uint4*)&sAh[lr][ls + 8] = rah1;
        *(uint4*)&sAl[lr][ls]     = ral0;  *(uint4*)&sAl[lr][ls + 8] = ral1;
        *(uint4*)&sBh[lr][ls]     = rbh0;  *(uint4*)&sBh[lr][ls + 8] = rbh1;
        *(uint4*)&sBl[lr][ls]     = rbl0;  *(uint4*)&sBl[lr][ls + 8] = rbl1;
        __syncthreads();
        if (k0 + 32 < DD) { LOAD8(k0 + 32) }

        #pragma unroll
        for (int ks = 0; ks < 32; ks += 16) {
            wmma::fragment<wmma::matrix_a, 16, 16, 16, __nv_bfloat16, wmma::row_major> ah[2], al[2];
            wmma::fragment<wmma::matrix_b, 16, 16, 16, __nv_bfloat16, wmma::col_major> bh[2], bl[2];
            #pragma unroll
            for (int i = 0; i < 2; i++) {
                wmma::load_matrix_sync(ah[i], &sAh[wr + 16 * i][ks], 32);
                wmma::load_matrix_sync(al[i], &sAl[wr + 16 * i][ks], 32);
            }
            #pragma unroll
            for (int j = 0; j < 2; j++) {
                wmma::load_matrix_sync(bh[j], &sBh[wc + 16 * j][ks], 32);
                wmma::load_matrix_sync(bl[j], &sBl[wc + 16 * j][ks], 32);
            }
            #pragma unroll
            for (int i = 0; i < 2; i++)
                #pragma unroll
                for (int j = 0; j < 2; j++) {
                    wmma::mma_sync(c[i][j], ah[i], bh[j], c[i][j]);
                    wmma::mma_sync(c[i][j], ah[i], bl[j], c[i][j]);
                    wmma::mma_sync(c[i][j], al[i], bh[j], c[i][j]);
                }
        }
    }
    #undef LOAD8

    #pragma unroll
    for (int i = 0; i < 2; i++)
        #pragma unroll
        for (int j = 0; j < 2; j++)
            wmma::store_matrix_sync(
                C + (size_t)(row0 + wr + 16 * i) * DD + col0 + wc + 16 * j,
                c[i][j], DD, wmma::mem_row_major);
}

// ---------------------------------------------------------------------------
// Tensor-core NN GEMM on pre-split bf16: g_ktil = kfull @ Wq
// BM=64, BN=32, BK=32, 128 threads (4 warps, each 32x16). grid (24, 16).
// ---------------------------------------------------------------------------
__global__ void __launch_bounds__(128) ktil_tc_nn()
{
    __shared__ __align__(16) __nv_bfloat16 sAh[64][32], sAl[64][32];
    __shared__ __align__(16) __nv_bfloat16 sBh[32][32], sBl[32][32];

    const int tid  = threadIdx.x;
    const int warp = tid >> 5;
    const int wr   = (warp & 1) * 32;
    const int wc   = (warp >> 1) * 16;
    const int row0 = blockIdx.y * 64;
    const int col0 = blockIdx.x * 32;

    wmma::fragment<wmma::accumulator, 16, 16, 16, float> c[2];
    wmma::fill_fragment(c[0], 0.f);
    wmma::fill_fragment(c[1], 0.f);

    const int lr = tid >> 1;
    const int ls = (tid & 1) * 16;
    const __nv_bfloat16* pAh = g_kfh + (size_t)(row0 + lr) * DD + ls;
    const __nv_bfloat16* pAl = g_kfl + (size_t)(row0 + lr) * DD + ls;
    const int br = tid >> 2;            // 0..31 (k row)
    const int bs = (tid & 3) * 8;       // 0..24 (n col)
    const __nv_bfloat16* pBh = g_wqh + (size_t)br * DD + col0 + bs;
    const __nv_bfloat16* pBl = g_wql + (size_t)br * DD + col0 + bs;

    uint4 rah0, rah1, ral0, ral1, rbh, rbl;
    #define LOAD6(k0)                                            \
        rah0 = *(const uint4*)(pAh + (k0));                      \
        rah1 = *(const uint4*)(pAh + (k0) + 8);                  \
        ral0 = *(const uint4*)(pAl + (k0));                      \
        ral1 = *(const uint4*)(pAl + (k0) + 8);                  \
        rbh  = *(const uint4*)(pBh + (size_t)(k0) * DD);         \
        rbl  = *(const uint4*)(pBl + (size_t)(k0) * DD);

    LOAD6(0)

    for (int k0 = 0; k0 < DD; k0 += 32) {
        __syncthreads();
        *(uint4*)&sAh[lr][ls]     = rah0;  *(uint4*)&sAh[lr][ls + 8] = rah1;
        *(uint4*)&sAl[lr][ls]     = ral0;  *(uint4*)&sAl[lr][ls + 8] = ral1;
        *(uint4*)&sBh[br][bs]     = rbh;
        *(uint4*)&sBl[br][bs]     = rbl;
        __syncthreads();
        if (k0 + 32 < DD) { LOAD6(k0 + 32) }

        #pragma unroll
        for (int ks = 0; ks < 32; ks += 16) {
            wmma::fragment<wmma::matrix_a, 16, 16, 16, __nv_bfloat16, wmma::row_major> ah[2], al[2];
            wmma::fragment<wmma::matrix_b, 16, 16, 16, __nv_bfloat16, wmma::row_major> bh, bl;
            #pragma unroll
            for (int i = 0; i < 2; i++) {
                wmma::load_matrix_sync(ah[i], &sAh[wr + 16 * i][ks], 32);
                wmma::load_matrix_sync(al[i], &sAl[wr + 16 * i][ks], 32);
            }
            wmma::load_matrix_sync(bh, &sBh[ks][wc], 32);
            wmma::load_matrix_sync(bl, &sBl[ks][wc], 32);
            #pragma unroll
            for (int i = 0; i < 2; i++) {
                wmma::mma_sync(c[i], ah[i], bh, c[i]);
                wmma::mma_sync(c[i], ah[i], bl, c[i]);
                wmma::mma_sync(c[i], al[i], bh, c[i]);
            }
        }
    }
    #undef LOAD6

    #pragma unroll
    for (int i = 0; i < 2; i++)
        wmma::store_matrix_sync(
            g_ktil + (size_t)(row0 + wr + 16 * i) * DD + col0 + wc,
            c[i], DD, wmma::mem_row_major);
}

// ---------------------------------------------------------------------------
// g_c[r] = dot(g_kfull[r,:], bq)
// ---------------------------------------------------------------------------
__global__ void __launch_bounds__(256) bias_dot_kernel(const float* __restrict__ bq)
{
    int row  = blockIdx.x * 8 + (threadIdx.x >> 5);
    int lane = threadIdx.x & 31;
    const float* r = g_kfull + (size_t)row * DD;
    float acc = 0.f;
    #pragma unroll
    for (int j = 0; j < DD / 32; j++)
        acc += r[lane + 32 * j] * bq[lane + 32 * j];
    #pragma unroll
    for (int o = 16; o; o >>= 1) acc += __shfl_xor_sync(0xffffffffu, acc, o);
    if (lane == 0) g_c[row] = acc;
}

// ===========================================================================
// Fused attention (unchanged from R6): t-group of 4, cp.async q staging,
// k-row prefetch overlapping the stage wait.
// ===========================================================================
#define STAGE_FLOATS (TG * 8 * 384)
#define STAGE_BYTES  (STAGE_FLOATS * 4)

__device__ __forceinline__ void cp_async16(uint32_t dst, const void* src) {
    asm volatile("cp.async.cg.shared.global [%0], [%1], 16;\n" :: "r"(dst), "l"(src) : "memory");
}

__global__ void __launch_bounds__(256) attn_kernel(const float* __restrict__ query,
                                                   float* __restrict__ out)
{
    extern __shared__ float sq[];
    __shared__ float s_sc[TG][LL];
    __shared__ float s_attn[TG][LL];

    const int t0   = blockIdx.x * TG;
    const int b    = blockIdx.y;
    const int tid  = threadIdx.x;
    const int wid  = tid >> 5;
    const int lane = tid & 31;

    const float rs = 0.03608439182435161f;

    const uint32_t smq = (uint32_t)__cvta_generic_to_shared(sq);

    const int tt_w  = tid >> 3;
    const int cw_tt = tt_w >> 3;
    const int cw_w  = tt_w & 7;
    const int colb  = tid & 7;

    const float4* kb = (const float4*)g_ktil + (size_t)b * LL * (DD / 4);

    float acc[TG];
    #pragma unroll
    for (int tt = 0; tt < TG; tt++) acc[tt] = 0.f;

    {
        const float* src = query + ((size_t)(b * TT + t0 + cw_tt) * LL + cw_w) * DD;
        uint32_t dst = smq + (uint32_t)(tt_w * 96) * 16;
        #pragma unroll
        for (int j = 0; j < 12; j++) {
            int c4 = colb + 8 * j;
            cp_async16(dst + c4 * 16, src + c4 * 4);
        }
        asm volatile("cp.async.commit_group;\n" ::: "memory");
    }

    float4 k0, k1, k2;
    {
        const float4* krow = kb + (size_t)wid * 192;
        k0 = krow[lane]; k1 = krow[lane + 32]; k2 = krow[lane + 64];
    }

    for (int c = 0; c < 16; c++) {
        float4 n0, n1, n2;
        if (c < 15) {
            const int lg = (c + 1) >> 1, h = (c + 1) & 1;
            const float* src = query +
                ((size_t)(b * TT + t0 + cw_tt) * LL + (lg * 8 + cw_w)) * DD + h * 384;
            uint32_t dst = smq + (uint32_t)(((c + 1) & 1) * STAGE_BYTES)
                               + (uint32_t)(tt_w * 96) * 16;
            #pragma unroll
            for (int j = 0; j < 12; j++) {
                int c4 = colb + 8 * j;
                cp_async16(dst + c4 * 16, src + c4 * 4);
            }
            asm volatile("cp.async.commit_group;\n" ::: "memory");
            const float4* krow = kb + (size_t)(lg * 8 + wid) * 192 + h * 96;
            n0 = krow[lane]; n1 = krow[lane + 32]; n2 = krow[lane + 64];
            asm volatile("cp.async.wait_group 1;\n" ::: "memory");
        } else {
            asm volatile("cp.async.wait_group 0;\n" ::: "memory");
        }
        __syncthreads();

        const int lg = c >> 1, h = c & 1;
        const int l = lg * 8 + wid;
        const float4* sqf = (const float4*)(sq + (c & 1) * STAGE_FLOATS);

        #pragma unroll
        for (int tt = 0; tt < TG; tt++) {
            const float4* qs = sqf + (tt * 8 + wid) * 96;
            float4 q0 = qs[lane], q1 = qs[lane + 32], q2 = qs[lane + 64];
            acc[tt] += q0.x * k0.x + q0.y * k0.y + q0.z * k0.z + q0.w * k0.w
                     + q1.x * k1.x + q1.y * k1.y + q1.z * k1.z + q1.w * k1.w
                     + q2.x * k2.x + q2.y * k2.y + q2.z * k2.z + q2.w * k2.w;
        }

        if (h == 1) {
            #pragma unroll
            for (int tt = 0; tt < TG; tt++) {
                float r = acc[tt];
                #pragma unroll
                for (int o = 16; o; o >>= 1) r += __shfl_xor_sync(0xffffffffu, r, o);
                if (lane == 0) s_sc[tt][l] = (r + g_c[b * LL + l]) * rs;
                acc[tt] = 0.f;
            }
        }
        __syncthreads();

        k0 = n0; k1 = n1; k2 = n2;
    }

    if (wid < TG) {
        float v0 = s_sc[wid][lane], v1 = s_sc[wid][lane + 32];
        float m = fmaxf(v0, v1);
        #pragma unroll
        for (int o = 16; o; o >>= 1) m = fmaxf(m, __shfl_xor_sync(0xffffffffu, m, o));
        float e0 = expf(v0 - m), e1 = expf(v1 - m);
        float s = e0 + e1;
        #pragma unroll
        for (int o = 16; o; o >>= 1) s += __shfl_xor_sync(0xffffffffu, s, o);
        float inv = 1.f / s;
        s_attn[wid][lane]      = e0 * inv;
        s_attn[wid][lane + 32] = e1 * inv;
    }
    __syncthreads();

    const float4* vb = (const float4*)g_vfull + (size_t)b * LL * 192;
    #pragma unroll 1
    for (int l = wid; l < LL; l += 8) {
        const float4* vr = vb + (size_t)l * 192;
        float4 v0 = vr[lane], v1 = vr[lane + 32], v2 = vr[lane + 64],
               v3 = vr[lane + 96], v4 = vr[lane + 128], v5 = vr[lane + 160];
        #pragma unroll
        for (int tt = 0; tt < TG; tt++) {
            const float a = s_attn[tt][l];
            float4* orow = (float4*)out + ((size_t)(b * TT + t0 + tt) * LL + l) * 192;
            orow[lane]       = make_float4(a * v0.x, a * v0.y, a * v0.z, a * v0.w);
            orow[lane + 32]  = make_float4(a * v1.x, a * v1.y, a * v1.z, a * v1.w);
            orow[lane + 64]  = make_float4(a * v2.x, a * v2.y, a * v2.z, a * v2.w);
            orow[lane + 96]  = make_float4(a * v3.x, a * v3.y, a * v3.z, a * v3.w);
            orow[lane + 128] = make_float4(a * v4.x, a * v4.y, a * v4.z, a * v4.w);
            orow[lane + 160] = make_float4(a * v5.x, a * v5.y, a * v5.z, a * v5.w);
        }
    }
}

// ---------------------------------------------------------------------------
extern "C" void kernel_launch(void* const* d_in, const int* in_sizes, int n_in,
                              void* d_out, int out_size)
{
    const float* query = (const float*)d_in[0];
    const float* key   = (const float*)d_in[1];
    const float* value = (const float*)d_in[2];
    const float* Wq    = (const float*)d_in[3];
    const float* bq    = (const float*)d_in[4];
    const float* Wk    = (const float*)d_in[5];
    const float* bk    = (const float*)d_in[6];
    const float* Wv    = (const float*)d_in[7];
    const float* bv    = (const float*)d_in[8];
    float* out = (float*)d_out;

    static int smem_set = 0;
    if (!smem_set) {
        cudaFuncSetAttribute(attn_kernel, cudaFuncAttributeMaxDynamicSharedMemorySize,
                             2 * STAGE_BYTES);
        smem_set = 1;
    }

    convert_inputs<<<dim3(NKV / 2048, 5), 256>>>(key, value, Wk, Wv, Wq);
    proj_tc_nt<<<dim3(DD / 64, (BB * LL) / 64, 2), 128>>>(bk, bv);
    convert_kf<<<NKV / 2048, 256>>>();
    bias_dot_kernel<<<(BB * LL) / 8, 256>>>(bq);
    ktil_tc_nn<<<dim3(DD / 32, (BB * LL) / 64), 128>>>();
    attn_kernel<<<dim3(TT / TG, BB), 256, 2 * STAGE_BYTES>>>(query, out);
}

// round 9
// speedup vs baseline: 1.0272x; 1.0272x over previous
#include <cstdint>
#include <cuda_runtime.h>
#include <cuda_bf16.h>
#include <mma.h>
#include <math.h>

using namespace nvcuda;

// Shapes (fixed): B=16, T=128, L=64, D=768
#define BB 16
#define TT 128
#define LL 64
#define DD 768
#define TG 4
#define NKV (BB * LL * DD)   // 786432
#define NW  (DD * DD)        // 589824

__device__ float g_ktil [NKV];
__device__ float g_vfull[NKV];
__device__ float g_c    [BB * LL];
__device__ float g_G    [NW];
__device__ float g_u    [DD];
__device__ float g_w    [DD];

__device__ __nv_bfloat16 g_keyh[NKV], g_keyl[NKV];
__device__ __nv_bfloat16 g_valh[NKV], g_vall[NKV];
__device__ __nv_bfloat16 g_wvh [NW],  g_wvl [NW];
__device__ __nv_bfloat16 g_wqth[NW],  g_wqtl[NW];   // split of Wq^T
__device__ __nv_bfloat16 g_wkth[NW],  g_wktl[NW];   // split of Wk^T
__device__ __nv_bfloat16 g_Gh  [NW],  g_Gl  [NW];

// ===========================================================================
// helpers
// ===========================================================================
__device__ __forceinline__ void split8(const float* src,
                                       __nv_bfloat16* hi, __nv_bfloat16* lo)
{
    float4 a = *(const float4*)(src);
    float4 b = *(const float4*)(src + 4);
    float v[8] = {a.x, a.y, a.z, a.w, b.x, b.y, b.z, b.w};
    __nv_bfloat16 h[8], l[8];
    #pragma unroll
    for (int i = 0; i < 8; i++) {
        h[i] = __float2bfloat16(v[i]);
        l[i] = __float2bfloat16(v[i] - __bfloat162float(h[i]));
    }
    *(uint4*)hi = *(uint4*)h;
    *(uint4*)lo = *(uint4*)l;
}

__device__ __forceinline__ uint32_t s2u(const void* p) {
    uint32_t a;
    asm("{ .reg .u64 t; cvta.to.shared.u64 t, %1; cvt.u32.u64 %0, t; }"
        : "=r"(a) : "l"(p));
    return a;
}

__device__ __forceinline__ void cp_async16(uint32_t dst, const void* src) {
    asm volatile("cp.async.cg.shared.global [%0], [%1], 16;\n" :: "r"(dst), "l"(src) : "memory");
}

// ===========================================================================
// conversion / small kernels
// ===========================================================================
__global__ void __launch_bounds__(256) convert_straight(
    const float* __restrict__ key, const float* __restrict__ value,
    const float* __restrict__ Wv)
{
    const float* src; __nv_bfloat16 *hi, *lo; int n;
    switch (blockIdx.y) {
        case 0:  src = key;   hi = g_keyh; lo = g_keyl; n = NKV; break;
        case 1:  src = value; hi = g_valh; lo = g_vall; n = NKV; break;
        default: src = Wv;    hi = g_wvh;  lo = g_wvl;  n = NW;  break;
    }
    int idx = (blockIdx.x * 256 + threadIdx.x) * 8;
    if (idx >= n) return;
    split8(src + idx, hi + idx, lo + idx);
}

// transposed splits: wqt[e][d] = Wq[d][e], wkt[f][d] = Wk[d][f]
__global__ void __launch_bounds__(256) transpose_split(
    const float* __restrict__ Wq, const float* __restrict__ Wk)
{
    __shared__ float t[32][33];
    const float* W = blockIdx.z ? Wk : Wq;
    __nv_bfloat16* oh = blockIdx.z ? g_wkth : g_wqth;
    __nv_bfloat16* ol = blockIdx.z ? g_wktl : g_wqtl;
    int d0 = blockIdx.x * 32, e0 = blockIdx.y * 32;
    int tx = threadIdx.x & 31, ty = threadIdx.x >> 5;
    #pragma unroll
    for (int i = 0; i < 4; i++)
        t[ty + 8 * i][tx] = W[(size_t)(d0 + ty + 8 * i) * DD + e0 + tx];
    __syncthreads();
    #pragma unroll
    for (int i = 0; i < 4; i++) {
        int e = e0 + ty + 8 * i, d = d0 + tx;
        float v = t[tx][ty + 8 * i];
        __nv_bfloat16 h = __float2bfloat16(v);
        oh[(size_t)e * DD + d] = h;
        ol[(size_t)e * DD + d] = __float2bfloat16(v - __bfloat162float(h));
    }
}

// u = Wq^T bk (y=0), w = Wk^T bq (y=1). grid (3,2) x 256.
__global__ void __launch_bounds__(256) matvec_uw(
    const float* __restrict__ Wq, const float* __restrict__ bk,
    const float* __restrict__ Wk, const float* __restrict__ bq)
{
    int e = blockIdx.x * 256 + threadIdx.x;
    const float* W  = blockIdx.y ? Wk : Wq;
    const float* bb = blockIdx.y ? bq : bk;
    float acc = 0.f;
    for (int d = 0; d < DD; d++) acc += W[(size_t)d * DD + e] * bb[d];
    (blockIdx.y ? g_w : g_u)[e] = acc;
}

// x<288: split G -> g_Gh/g_Gl.  x>=288: c[row] = key[row]·w + bq·bk
__global__ void __launch_bounds__(256) splitG_ckey(
    const float* __restrict__ key, const float* __restrict__ bq,
    const float* __restrict__ bk)
{
    int x = blockIdx.x;
    if (x < 288) {
        int idx = (x * 256 + threadIdx.x) * 8;
        split8(g_G + idx, g_Gh + idx, g_Gl + idx);
    } else {
        int row  = (x - 288) * 8 + (threadIdx.x >> 5);
        int lane = threadIdx.x & 31;
        const float* r = key + (size_t)row * DD;
        float acc = 0.f, s0 = 0.f;
        #pragma unroll
        for (int j = 0; j < DD / 32; j++) {
            acc += r[lane + 32 * j] * g_w[lane + 32 * j];
            s0  += bq[lane + 32 * j] * bk[lane + 32 * j];
        }
        #pragma unroll
        for (int o = 16; o; o >>= 1) {
            acc += __shfl_xor_sync(0xffffffffu, acc, o);
            s0  += __shfl_xor_sync(0xffffffffu, s0, o);
        }
        if (lane == 0) g_c[row] = acc + s0;
    }
}

// ===========================================================================
// wmma NT GEMM on pre-split bf16, cp.async double-buffered.
// C[r,n] = sum_k (Ah+Al)[r,k] * (Bh+Bl)[n,k] + bias[n]
//        ~ ah*bh + ah*bl + al*bh  (fp32 accumulate)
// BM=128, BN=64, BK=32. 256 threads = 8 warps (4x2 of 32x32).
// smem rows padded to 40 bf16 (80B) for conflict-free ldmatrix.
// Dynamic smem: A hi/lo 2st x 128x40, B hi/lo 2st x 64x40, biasTile 16x64.
// ===========================================================================
#define GSM_AH 0
#define GSM_AL 20480
#define GSM_BH 40960
#define GSM_BL 51200
#define GSM_BT 61440
#define GSM_TOTAL 65536

__device__ __forceinline__ void wgemm_nt(
    const __nv_bfloat16* __restrict__ Ah, const __nv_bfloat16* __restrict__ Al,
    const __nv_bfloat16* __restrict__ Bh, const __nv_bfloat16* __restrict__ Bl,
    const float* __restrict__ bias, float* __restrict__ C,
    int row0, int col0)
{
    extern __shared__ char dsm[];
    __nv_bfloat16* sAh = (__nv_bfloat16*)(dsm + GSM_AH);   // [2][128*40]
    __nv_bfloat16* sAl = (__nv_bfloat16*)(dsm + GSM_AL);
    __nv_bfloat16* sBh = (__nv_bfloat16*)(dsm + GSM_BH);   // [2][64*40]
    __nv_bfloat16* sBl = (__nv_bfloat16*)(dsm + GSM_BL);
    float* biasTile    = (float*)(dsm + GSM_BT);           // [16][64]

    const uint32_t uAh = s2u(sAh), uAl = s2u(sAl), uBh = s2u(sBh), uBl = s2u(sBl);

    const int tid  = threadIdx.x;
    const int warp = tid >> 5;
    const int wr   = (warp >> 1) * 32;   // 0,32,64,96
    const int wc   = (warp & 1) * 32;    // 0,32

    // bias tile (16 identical rows -> accumulator init)
    for (int idx = tid; idx < 1024; idx += 256) {
        int col = idx & 63;
        biasTile[idx] = bias ? bias[col0 + col] : 0.f;
    }
    __syncthreads();

    wmma::fragment<wmma::accumulator, 16, 16, 16, float> c[2][2];
    #pragma unroll
    for (int i = 0; i < 2; i++)
        #pragma unroll
        for (int j = 0; j < 2; j++)
            wmma::load_matrix_sync(c[i][j], &biasTile[0 * 64 + wc + 16 * j], 64,
                                   wmma::mem_row_major);

    // cp.async mapping
    const int ar = tid >> 1;          // A row 0..127
    const int as = (tid & 1) * 2;     // A seg base (16B units): 0 or 2
    const int br = tid >> 2;          // B row 0..63
    const int bs = tid & 3;           // B seg

    const __nv_bfloat16* pAh0 = Ah + (size_t)(row0 + ar) * DD + as * 8;
    const __nv_bfloat16* pAl0 = Al + (size_t)(row0 + ar) * DD + as * 8;
    const __nv_bfloat16* pBh0 = Bh + (size_t)(col0 + br) * DD + bs * 8;
    const __nv_bfloat16* pBl0 = Bl + (size_t)(col0 + br) * DD + bs * 8;

    #define ISSUE(st) do {                                                   \
        if ((st) < 24) {                                                     \
            int _buf = (st) & 1, _k0 = (st) * 32;                            \
            uint32_t dA = (uint32_t)(_buf * 10240 + ar * 80 + as * 16);      \
            cp_async16(uAh + dA,      pAh0 + _k0);                           \
            cp_async16(uAh + dA + 16, pAh0 + _k0 + 8);                       \
            cp_async16(uAl + dA,      pAl0 + _k0);                           \
            cp_async16(uAl + dA + 16, pAl0 + _k0 + 8);                       \
            uint32_t dB = (uint32_t)(_buf * 5120 + br * 80 + bs * 16);       \
            cp_async16(uBh + dB, pBh0 + _k0);                                \
            cp_async16(uBl + dB, pBl0 + _k0);                                \
        }                                                                    \
        asm volatile("cp.async.commit_group;\n" ::: "memory");               \
    } while (0)

    ISSUE(0);
    ISSUE(1);

    for (int st = 0; st < 24; st++) {
        asm volatile("cp.async.wait_group 1;\n" ::: "memory");
        __syncthreads();
        const int buf = st & 1;
        const __nv_bfloat16* bAh = sAh + buf * 5120;
        const __nv_bfloat16* bAl = sAl + buf * 5120;
        const __nv_bfloat16* bBh = sBh + buf * 2560;
        const __nv_bfloat16* bBl = sBl + buf * 2560;

        #pragma unroll
        for (int ks = 0; ks < 2; ks++) {
            wmma::fragment<wmma::matrix_a, 16, 16, 16, __nv_bfloat16, wmma::row_major> ah[2], al[2];
            wmma::fragment<wmma::matrix_b, 16, 16, 16, __nv_bfloat16, wmma::col_major> bh[2], bl[2];
            #pragma unroll
            for (int i = 0; i < 2; i++) {
                wmma::load_matrix_sync(ah[i], bAh + (wr + 16 * i) * 40 + ks * 16, 40);
                wmma::load_matrix_sync(al[i], bAl + (wr + 16 * i) * 40 + ks * 16, 40);
            }
            #pragma unroll
            for (int j = 0; j < 2; j++) {
                wmma::load_matrix_sync(bh[j], bBh + (wc + 16 * j) * 40 + ks * 16, 40);
                wmma::load_matrix_sync(bl[j], bBl + (wc + 16 * j) * 40 + ks * 16, 40);
            }
            #pragma unroll
            for (int i = 0; i < 2; i++)
                #pragma unroll
                for (int j = 0; j < 2; j++) {
                    wmma::mma_sync(c[i][j], ah[i], bh[j], c[i][j]);
                    wmma::mma_sync(c[i][j], ah[i], bl[j], c[i][j]);
                    wmma::mma_sync(c[i][j], al[i], bh[j], c[i][j]);
                }
        }
        __syncthreads();
        ISSUE(st + 2);
    }
    #undef ISSUE

    #pragma unroll
    for (int i = 0; i < 2; i++)
        #pragma unroll
        for (int j = 0; j < 2; j++)
            wmma::store_matrix_sync(
                C + (size_t)(row0 + wr + 16 * i) * DD + col0 + wc + 16 * j,
                c[i][j], DD, wmma::mem_row_major);
}

// L1: blocks 0..71 -> G = Wq^T@Wk (768x768); 72..167 -> vfull = value@Wv^T+bv
__global__ void __launch_bounds__(256) wg_L1(const float* __restrict__ bv)
{
    int x = blockIdx.x;
    if (x < 72)
        wgemm_nt(g_wqth, g_wqtl, g_wkth, g_wktl, nullptr, g_G,
                 (x / 12) * 128, (x % 12) * 64);
    else {
        x -= 72;
        wgemm_nt(g_valh, g_vall, g_wvh, g_wvl, bv, g_vfull,
                 (x / 12) * 128, (x % 12) * 64);
    }
}

// L2: ktil = key @ G^T + u  (1024x768)
__global__ void __launch_bounds__(256) wg_L2()
{
    int x = blockIdx.x;
    wgemm_nt(g_keyh, g_keyl, g_Gh, g_Gl, g_u, g_ktil,
             (x / 12) * 128, (x % 12) * 64);
}

// ===========================================================================
// Fused attention (identical to R6 best)
// ===========================================================================
#define STAGE_FLOATS (TG * 8 * 384)
#define STAGE_BYTES  (STAGE_FLOATS * 4)

__global__ void __launch_bounds__(256) attn_kernel(const float* __restrict__ query,
                                                   float* __restrict__ out)
{
    extern __shared__ float sq[];
    __shared__ float s_sc[TG][LL];
    __shared__ float s_attn[TG][LL];

    const int t0   = blockIdx.x * TG;
    const int b    = blockIdx.y;
    const int tid  = threadIdx.x;
    const int wid  = tid >> 5;
    const int lane = tid & 31;

    const float rs = 0.03608439182435161f;

    const uint32_t smq = (uint32_t)__cvta_generic_to_shared(sq);

    const int tt_w  = tid >> 3;
    const int cw_tt = tt_w >> 3;
    const int cw_w  = tt_w & 7;
    const int colb  = tid & 7;

    const float4* kb = (const float4*)g_ktil + (size_t)b * LL * (DD / 4);

    float acc[TG];
    #pragma unroll
    for (int tt = 0; tt < TG; tt++) acc[tt] = 0.f;

    {
        const float* src = query + ((size_t)(b * TT + t0 + cw_tt) * LL + cw_w) * DD;
        uint32_t dst = smq + (uint32_t)(tt_w * 96) * 16;
        #pragma unroll
        for (int j = 0; j < 12; j++) {
            int c4 = colb + 8 * j;
            cp_async16(dst + c4 * 16, src + c4 * 4);
        }
        asm volatile("cp.async.commit_group;\n" ::: "memory");
    }

    float4 k0, k1, k2;
    {
        const float4* krow = kb + (size_t)wid * 192;
        k0 = krow[lane]; k1 = krow[lane + 32]; k2 = krow[lane + 64];
    }

    for (int c = 0; c < 16; c++) {
        float4 n0, n1, n2;
        if (c < 15) {
            const int lg = (c + 1) >> 1, h = (c + 1) & 1;
            const float* src = query +
                ((size_t)(b * TT + t0 + cw_tt) * LL + (lg * 8 + cw_w)) * DD + h * 384;
            uint32_t dst = smq + (uint32_t)(((c + 1) & 1) * STAGE_BYTES)
                               + (uint32_t)(tt_w * 96) * 16;
            #pragma unroll
            for (int j = 0; j < 12; j++) {
                int c4 = colb + 8 * j;
                cp_async16(dst + c4 * 16, src + c4 * 4);
            }
            asm volatile("cp.async.commit_group;\n" ::: "memory");
            const float4* krow = kb + (size_t)(lg * 8 + wid) * 192 + h * 96;
            n0 = krow[lane]; n1 = krow[lane + 32]; n2 = krow[lane + 64];
            asm volatile("cp.async.wait_group 1;\n" ::: "memory");
        } else {
            asm volatile("cp.async.wait_group 0;\n" ::: "memory");
        }
        __syncthreads();

        const int lg = c >> 1, h = c & 1;
        const int l = lg * 8 + wid;
        const float4* sqf = (const float4*)(sq + (c & 1) * STAGE_FLOATS);

        #pragma unroll
        for (int tt = 0; tt < TG; tt++) {
            const float4* qs = sqf + (tt * 8 + wid) * 96;
            float4 q0 = qs[lane], q1 = qs[lane + 32], q2 = qs[lane + 64];
            acc[tt] += q0.x * k0.x + q0.y * k0.y + q0.z * k0.z + q0.w * k0.w
                     + q1.x * k1.x + q1.y * k1.y + q1.z * k1.z + q1.w * k1.w
                     + q2.x * k2.x + q2.y * k2.y + q2.z * k2.z + q2.w * k2.w;
        }

        if (h == 1) {
            #pragma unroll
            for (int tt = 0; tt < TG; tt++) {
                float r = acc[tt];
                #pragma unroll
                for (int o = 16; o; o >>= 1) r += __shfl_xor_sync(0xffffffffu, r, o);
                if (lane == 0) s_sc[tt][l] = (r + g_c[b * LL + l]) * rs;
                acc[tt] = 0.f;
            }
        }
        __syncthreads();

        k0 = n0; k1 = n1; k2 = n2;
    }

    if (wid < TG) {
        float v0 = s_sc[wid][lane], v1 = s_sc[wid][lane + 32];
        float m = fmaxf(v0, v1);
        #pragma unroll
        for (int o = 16; o; o >>= 1) m = fmaxf(m, __shfl_xor_sync(0xffffffffu, m, o));
        float e0 = expf(v0 - m), e1 = expf(v1 - m);
        float s = e0 + e1;
        #pragma unroll
        for (int o = 16; o; o >>= 1) s += __shfl_xor_sync(0xffffffffu, s, o);
        float inv = 1.f / s;
        s_attn[wid][lane]      = e0 * inv;
        s_attn[wid][lane + 32] = e1 * inv;
    }
    __syncthreads();

    const float4* vb = (const float4*)g_vfull + (size_t)b * LL * 192;
    #pragma unroll 1
    for (int l = wid; l < LL; l += 8) {
        const float4* vr = vb + (size_t)l * 192;
        float4 v0 = vr[lane], v1 = vr[lane + 32], v2 = vr[lane + 64],
               v3 = vr[lane + 96], v4 = vr[lane + 128], v5 = vr[lane + 160];
        #pragma unroll
        for (int tt = 0; tt < TG; tt++) {
            const float a = s_attn[tt][l];
            float4* orow = (float4*)out + ((size_t)(b * TT + t0 + tt) * LL + l) * 192;
            orow[lane]       = make_float4(a * v0.x, a * v0.y, a * v0.z, a * v0.w);
            orow[lane + 32]  = make_float4(a * v1.x, a * v1.y, a * v1.z, a * v1.w);
            orow[lane + 64]  = make_float4(a * v2.x, a * v2.y, a * v2.z, a * v2.w);
            orow[lane + 96]  = make_float4(a * v3.x, a * v3.y, a * v3.z, a * v3.w);
            orow[lane + 128] = make_float4(a * v4.x, a * v4.y, a * v4.z, a * v4.w);
            orow[lane + 160] = make_float4(a * v5.x, a * v5.y, a * v5.z, a * v5.w);
        }
    }
}

// ---------------------------------------------------------------------------
extern "C" void kernel_launch(void* const* d_in, const int* in_sizes, int n_in,
                              void* d_out, int out_size)
{
    const float* query = (const float*)d_in[0];
    const float* key   = (const float*)d_in[1];
    const float* value = (const float*)d_in[2];
    const float* Wq    = (const float*)d_in[3];
    const float* bq    = (const float*)d_in[4];
    const float* Wk    = (const float*)d_in[5];
    const float* bk    = (const float*)d_in[6];
    const float* Wv    = (const float*)d_in[7];
    const float* bv    = (const float*)d_in[8];
    float* out = (float*)d_out;

    static int attr_set = 0;
    if (!attr_set) {
        cudaFuncSetAttribute(attn_kernel, cudaFuncAttributeMaxDynamicSharedMemorySize,
                             2 * STAGE_BYTES);
        cudaFuncSetAttribute(wg_L1, cudaFuncAttributeMaxDynamicSharedMemorySize,
                             GSM_TOTAL);
        cudaFuncSetAttribute(wg_L2, cudaFuncAttributeMaxDynamicSharedMemorySize,
                             GSM_TOTAL);
        attr_set = 1;
    }

    convert_straight<<<dim3(NKV / 2048, 3), 256>>>(key, value, Wv);
    transpose_split<<<dim3(24, 24, 2), 256>>>(Wq, Wk);
    matvec_uw<<<dim3(3, 2), 256>>>(Wq, bk, Wk, bq);
    wg_L1<<<168, 256, GSM_TOTAL>>>(bv);
    splitG_ckey<<<416, 256>>>(key, bq, bk);
    wg_L2<<<96, 256, GSM_TOTAL>>>();
    attn_kernel<<<dim3(TT / TG, BB), 256, 2 * STAGE_BYTES>>>(query, out);
}